// round 11
// baseline (speedup 1.0000x reference)
#include <cuda_runtime.h>
#include <cstdint>

typedef unsigned long long u64;
typedef unsigned int u32;

#define Nn 8
#define Cc 80
#define HWp 25600
#define PER_IMG (Cc*HWp)        // 2048000
#define FINE 64
#define FINE_BASE 8089          // (SPEC_BITS >> 17)
#define CAP 4096
#define CAP_SPEC 65536
#define KP 1024
#define KK 1000
#define POST 100
#define SPEC_BITS 0x3F333333u   /* bits of 0.70f */
#define REJECT_X 0.8400f        /* conservative: sigmoid(0.84)=0.6985 < 0.70 */
#define CSTAGE 4096
#define SSTAGE 512
#define TILE_JOBS 136           /* 16*17/2 upper-triangular 64x64 tiles */

// ---------------- scratch (device globals; zero-init; counters re-zeroed by k_scanout) ----
__device__ u32   g_fine[Nn*FINE];
__device__ int   g_scnt[Nn];
__device__ int   g_fbforce[Nn];
__device__ u64   g_spec[Nn*CAP_SPEC];
__device__ float g_score[Nn*KP];
__device__ float g_boxes[Nn*KP*4];
__device__ int   g_label[Nn*KP];
__device__ u32   g_validw[Nn*32];
__device__ float g_maxo[Nn];
__device__ u64   g_mask[Nn*KP*16];

__device__ __forceinline__ float sigmoidf_(float x) {
    return 1.0f / (1.0f + expf(-x));
}

// ---------------- pass 1: stream cls, warp-aggregated compact, dense sigmoid, fine hist ----
__global__ void __launch_bounds__(256) k_hist(const float* __restrict__ cls,
                                              const float* __restrict__ ctr) {
    __shared__ float sx[CSTAGE];
    __shared__ u32   se[CSTAGE];
    __shared__ u64   stage[SSTAGE];
    __shared__ u32   fine[FINE];
    __shared__ int cstage_n, sstage_n, sbase;
    if (threadIdx.x < FINE) fine[threadIdx.x] = 0;
    if (threadIdx.x == 0) { cstage_n = 0; sstage_n = 0; }
    __syncthreads();
    int n = blockIdx.y;
    u32 lane = threadIdx.x & 31;
    u32 lt_mask = (1u << lane) - 1u;
    const float4* cls4 = (const float4*)(cls + (size_t)n*PER_IMG);
    int t4 = blockIdx.x*2048 + threadIdx.x;
    // Phase A: stream + warp-aggregated compact
    #pragma unroll
    for (int it = 0; it < 8; it++, t4 += 256) {
        float4 x = cls4[t4];
        int e = t4*4;
        float pv[4] = {x.x, x.y, x.z, x.w};
        #pragma unroll
        for (int k = 0; k < 4; k++) {
            bool pred = (pv[k] >= REJECT_X);
            u32 ballot = __ballot_sync(0xffffffffu, pred);
            if (ballot) {
                int base;
                if (lane == 0) base = atomicAdd(&cstage_n, __popc(ballot));
                base = __shfl_sync(0xffffffffu, base, 0);
                if (pred) {
                    int pos = base + __popc(ballot & lt_mask);
                    if (pos < CSTAGE) { sx[pos] = pv[k]; se[pos] = (u32)(e + k); }
                }
            }
        }
    }
    __syncthreads();
    int m = cstage_n; if (m > CSTAGE) m = CSTAGE;
    // Phase B: dense sigmoid on compacted list
    const float* ctrn = ctr + n*HWp;
    for (int i = threadIdx.x; i < m; i += 256) {
        float xv = sx[i];
        u32 e = se[i];
        u32 c = e / (u32)HWp;
        u32 pix = e - c*(u32)HWp;
        float p = sigmoidf_(xv);
        float cv = sigmoidf_(ctrn[pix]);
        float s = p*cv;
        u32 sb = __float_as_uint(s);
        if (p > 0.05f && sb >= SPEC_BITS) {
            atomicAdd(&fine[(sb >> 17) - FINE_BASE], 1u);
            u64 key = (((u64)(~sb)) << 32) | (u64)(pix*80u + c);
            int pos = atomicAdd(&sstage_n, 1);
            if (pos < SSTAGE) stage[pos] = key;
            else {
                int gp = atomicAdd(&g_scnt[n], 1);
                if (gp < CAP_SPEC) g_spec[n*CAP_SPEC + gp] = key;
            }
        }
    }
    __syncthreads();
    if (threadIdx.x < FINE) {
        u32 v = fine[threadIdx.x];
        if (v) atomicAdd(&g_fine[n*FINE + threadIdx.x], v);
    }
    int sm = sstage_n < SSTAGE ? sstage_n : SSTAGE;
    if (threadIdx.x == 0 && sm > 0) sbase = atomicAdd(&g_scnt[n], sm);
    __syncthreads();
    for (int i = threadIdx.x; i < sm; i += 256) {
        int gp = sbase + i;
        if (gp < CAP_SPEC) g_spec[n*CAP_SPEC + gp] = stage[i];
    }
    if (threadIdx.x == 0 && cstage_n > CSTAGE) g_fbforce[n] = 1;
}

// ---------------- fused threshold + filter + bitonic sort + box decode + max_c ----------
__global__ void __launch_bounds__(1024) k_sortdecode(const float* __restrict__ cls,
                                                     const float* __restrict__ ctr,
                                                     const float* __restrict__ reg,
                                                     const float* __restrict__ pts,
                                                     const float* __restrict__ imsz) {
    __shared__ u64 sk[CAP];           // reused as u32[8192] hist in parachute
    __shared__ float red[1024];
    __shared__ int cnt_s;
    __shared__ int fb_s;
    __shared__ u32 tb_s;
    int n = blockIdx.x, tid = threadIdx.x;
    // threshold from fine histogram (fast path)
    if (tid == 0) {
        u32 cum = 0; int fstar = -1;
        for (int f = FINE - 1; f >= 1; f--) {
            cum += g_fine[n*FINE + f];
            if (cum >= (u32)KK) { fstar = f; break; }
        }
        int fb = (fstar < 0) || (g_scnt[n] > CAP_SPEC) || g_fbforce[n];
        fb_s = fb;
        tb_s = fb ? 0u : (((u32)(FINE_BASE + fstar)) << 17);
        cnt_s = 0;
    }
    __syncthreads();
    if (fb_s) {
        // parachute: exact full-range histogram using sk as u32[8192]
        u32* h = (u32*)sk;
        for (int i = tid; i < 8192; i += 1024) h[i] = 0;
        __syncthreads();
        const float* c0 = cls + (size_t)n*PER_IMG;
        const float* ctrn = ctr + n*HWp;
        for (int e = tid; e < PER_IMG; e += 1024) {
            int c = e / HWp; int pix = e - c*HWp;
            float p = sigmoidf_(c0[e]);
            if (p > 0.05f) {
                float cv = sigmoidf_(ctrn[pix]);
                u32 sb = __float_as_uint(p*cv);
                atomicAdd(&h[sb >> 17], 1u);
            }
        }
        __syncthreads();
        if (tid == 0) {
            u32 cum = 0; u32 tb = 0;
            for (int b = 8191; b >= 0; b--) {
                cum += h[b];
                if (cum >= (u32)KK) { tb = ((u32)b) << 17; break; }
            }
            tb_s = tb;
        }
        __syncthreads();
    }
    for (int i = tid; i < CAP; i += 1024) sk[i] = ~0ULL;
    __syncthreads();
    u32 tb = tb_s;
    if (!fb_s) {
        int m = g_scnt[n];
        for (int i = tid; i < m; i += 1024) {
            u64 key = g_spec[n*CAP_SPEC + i];
            u32 sb = ~((u32)(key >> 32));
            if (sb >= tb) {
                int pos = atomicAdd(&cnt_s, 1);
                if (pos < CAP) sk[pos] = key;
            }
        }
    } else {
        const float* c0 = cls + (size_t)n*PER_IMG;
        const float* ctrn = ctr + n*HWp;
        for (int e = tid; e < PER_IMG; e += 1024) {
            int c = e / HWp; int pix = e - c*HWp;
            float p = sigmoidf_(c0[e]);
            if (p > 0.05f) {
                float cv = sigmoidf_(ctrn[pix]);
                float s = p*cv;
                u32 sb = __float_as_uint(s);
                if (sb >= tb) {
                    int pos = atomicAdd(&cnt_s, 1);
                    if (pos < CAP) sk[pos] = (((u64)(~sb)) << 32) | (u64)((u32)pix*80u + (u32)c);
                }
            }
        }
    }
    __syncthreads();
    int cnt = cnt_s; if (cnt > CAP) cnt = CAP;
    int S = (cnt <= 2048) ? 2048 : 4096;
    for (int k2 = 2; k2 <= S; k2 <<= 1) {
        for (int j = k2 >> 1; j > 0; j >>= 1) {
            for (int i = tid; i < S; i += 1024) {
                int p = i ^ j;
                if (p > i) {
                    u64 a = sk[i], b = sk[p];
                    bool up = ((i & k2) == 0);
                    if ((a > b) == up) { sk[i] = b; sk[p] = a; }
                }
            }
            __syncthreads();
        }
    }
    float w1 = imsz[n*2] - 1.0f;
    float h1 = imsz[n*2 + 1] - 1.0f;
    const float* rg = reg + (size_t)n*4*HWp;
    float mx = 0.0f;
    {
        int r = tid;                       // KP == blockDim == 1024
        u64 key = sk[r];
        float val; int valid; u32 idx;
        if (key == ~0ULL || r >= KK) { val = -1.0f; valid = 0; idx = 0; }
        else {
            u32 sb = ~((u32)(key >> 32));
            val = __uint_as_float(sb);
            idx = (u32)key;
            valid = (val >= 0.0f) ? 1 : 0;
        }
        u32 c = idx % 80u;
        u32 loc = idx / 80u;
        float px = pts[loc*2], py = pts[loc*2 + 1];
        float d0 = rg[loc], d1 = rg[HWp + loc], d2 = rg[2*HWp + loc], d3 = rg[3*HWp + loc];
        float x1 = fminf(fmaxf(px - d0, 0.0f), w1);
        float y1 = fminf(fmaxf(py - d1, 0.0f), h1);
        float x2 = fminf(fmaxf(px + d2, 0.0f), w1);
        float y2 = fminf(fmaxf(py + d3, 0.0f), h1);
        int o = (n*KP + r)*4;
        g_boxes[o] = x1; g_boxes[o+1] = y1; g_boxes[o+2] = x2; g_boxes[o+3] = y2;
        g_label[n*KP + r] = (int)c + 1;
        g_score[n*KP + r] = valid ? sqrtf(fmaxf(val, 0.0f)) : -1.0f;
        // valid bitmap via ballot: 32 warps x 32 lanes = 1024 entries
        u32 bal = __ballot_sync(0xffffffffu, valid != 0);
        if ((tid & 31) == 0) g_validw[n*32 + (tid >> 5)] = bal;
        mx = valid ? fmaxf(fmaxf(x1, x2), fmaxf(y1, y2)) : 0.0f;
    }
    red[tid] = mx;
    __syncthreads();
    for (int s = 512; s > 0; s >>= 1) {
        if (tid < s) red[tid] = fmaxf(red[tid], red[tid + s]);
        __syncthreads();
    }
    if (tid == 0) g_maxo[n] = red[0] + 1.0f;
}

// ---------------- dense triangular IoU tiles: 4 tile-jobs per 256-thread block ----------
__global__ void __launch_bounds__(256) k_mask() {
    int jobLocal = threadIdx.x >> 6;       // 0..3
    int t = threadIdx.x & 63;
    int job = blockIdx.x*4 + jobLocal;     // 0..1087
    int n = job / TILE_JOBS;
    int q = job - n*TILE_JOBS;
    int ti = 0;
    for (int r = 0; r < 16; r++) {
        int cnt = 16 - r;
        if (q < cnt) { ti = r; break; }
        q -= cnt;
    }
    int tj = ti + q;
    float maxo = g_maxo[n];
    int i = ti*64 + t;
    int oi = (n*KP + i)*4;
    float offi = (float)g_label[n*KP + i] * maxo;
    float ax1 = g_boxes[oi]   + offi;
    float ay1 = g_boxes[oi+1] + offi;
    float ax2 = g_boxes[oi+2] + offi;
    float ay2 = g_boxes[oi+3] + offi;
    float areai = (ax2 - ax1)*(ay2 - ay1);
    __shared__ float sb[4][64][5];
    int j0 = tj*64 + t;
    int oj = (n*KP + j0)*4;
    float offj = (float)g_label[n*KP + j0] * maxo;
    float bx1 = g_boxes[oj]   + offj;
    float by1 = g_boxes[oj+1] + offj;
    float bx2 = g_boxes[oj+2] + offj;
    float by2 = g_boxes[oj+3] + offj;
    sb[jobLocal][t][0] = bx1;
    sb[jobLocal][t][1] = by1;
    sb[jobLocal][t][2] = bx2;
    sb[jobLocal][t][3] = by2;
    sb[jobLocal][t][4] = (bx2 - bx1)*(by2 - by1);
    __syncthreads();
    u64 bits = 0;
    if (i < KK) {
        int jbase = tj*64;
        const float (*sj)[5] = sb[jobLocal];
        #pragma unroll 4
        for (int jj = 0; jj < 64; jj++) {
            int j = jbase + jj;
            if (j <= i || j >= KK) continue;
            float xx1 = fmaxf(ax1, sj[jj][0]);
            float yy1 = fmaxf(ay1, sj[jj][1]);
            float xx2 = fminf(ax2, sj[jj][2]);
            float yy2 = fminf(ay2, sj[jj][3]);
            float inter = fmaxf(xx2 - xx1, 0.0f)*fmaxf(yy2 - yy1, 0.0f);
            float den = fmaxf(areai + sj[jj][4] - inter, 1e-6f);
            if (inter / den > 0.6f) bits |= 1ull << jj;
        }
    }
    g_mask[(size_t)(n*KP + i)*16 + tj] = bits;
}

// ---------------- fused NMS scan + top-100 output + counter cleanup ----------------
// 32-bit chunked serial scan: g_mask u64 rows aliased as u32[1024][32].
// Diag step = 3 dependent 32-bit ops (2 const shifts + LOP3); mm batched in regs.
// Cross-chunk OR: 31 owner lanes, 32 independent predicated LDS each.
__global__ void __launch_bounds__(256, 1) k_scanout(float* __restrict__ out, int out_size) {
    int n = blockIdx.x, t = threadIdx.x;
    __shared__ u32 buf[2][32][33];     // padded: diag stride-33 loads are conflict-free
    __shared__ u32 rem[32];
    __shared__ u32 keepw[32];
    const u32* gm32 = (const u32*)g_mask;
    if (t < 32) rem[t] = ~g_validw[n*32 + t];  // suppressed-or-invalid bits start set
    // preload chunk 0 (rows 0..31, all 32 words)
    for (int q = t; q < 1024; q += 256)
        buf[0][q >> 5][q & 31] = gm32[(size_t)(n*KP + (q >> 5))*32 + (q & 31)];
    __syncthreads();
    for (int c = 0; c < 32; c++) {
        u32 (*cur)[33] = buf[c & 1];
        u32 (*nxt)[33] = buf[(c + 1) & 1];
        if (t >= 32 && c < 31) {
            // threads 32..255 prefetch chunk c+1 while thread 0 resolves chunk c
            for (int q = t - 32; q < 1024; q += 224)
                nxt[q >> 5][q & 31] = gm32[(size_t)(n*KP + (c + 1)*32 + (q >> 5))*32 + (q & 31)];
        }
        if (t == 0) {
            u32 rcur = rem[c], kb = 0;
            #pragma unroll
            for (int g = 0; g < 4; g++) {
                u32 mm[8];
                #pragma unroll
                for (int b2 = 0; b2 < 8; b2++) mm[b2] = cur[g*8 + b2][c];
                #pragma unroll
                for (int b2 = 0; b2 < 8; b2++) {
                    int b = g*8 + b2;
                    u32 dead_mask = (u32)(((int)(rcur << (31 - b))) >> 31); // all-ones if bit b set
                    kb |= (~dead_mask) & (1u << b);
                    rcur |= mm[b2] & ~dead_mask;
                }
            }
            rem[c] = rcur;
            keepw[c] = kb;
        }
        __syncthreads();
        if (t > c && t < 32) {
            u32 kb = keepw[c];
            u32 acc = rem[t];
            #pragma unroll 8
            for (int b = 0; b < 32; b++) {
                u32 sel = 0u - ((kb >> b) & 1u);
                acc |= cur[b][t] & sel;
            }
            rem[t] = acc;
        }
        __syncthreads();
    }
    __shared__ int offs[32], noffs[32];
    __shared__ int cnts[32], ncnts[32];
    __shared__ int list[POST];
    __shared__ int mks;
    if (t < 32) {
        u32 vmask = (t == 31) ? 0xFFu : 0xFFFFFFFFu;   // bits i < 1000
        cnts[t]  = __popc(keepw[t]);
        ncnts[t] = __popc(~keepw[t] & vmask);
    }
    __syncthreads();
    if (t == 0) {
        int acc = 0;
        for (int w = 0; w < 32; w++) { offs[w] = acc; acc += cnts[w]; }
        mks = acc > POST ? POST : acc;
        int acc2 = 0;
        for (int w = 0; w < 32; w++) { noffs[w] = acc2; acc2 += ncnts[w]; }
    }
    __syncthreads();
    if (t < 32) {
        u32 w = keepw[t];
        int off = offs[t];
        while (w && off < POST) { int b = __ffs(w) - 1; list[off++] = t*32 + b; w &= w - 1; }
        u32 vmask = (t == 31) ? 0xFFu : 0xFFFFFFFFu;
        u32 nw = ~keepw[t] & vmask;
        int noff = mks + noffs[t];
        while (nw && noff < POST) { int b = __ffs(nw) - 1; list[noff++] = t*32 + b; nw &= nw - 1; }
    }
    __syncthreads();
    if (t < POST) {
        int j = list[t];
        bool ov = t < mks;
        int ob = (n*KP + j)*4;
        int base = n*POST*5 + t*5;
        if (base + 4 < out_size) {
            out[base]     = g_boxes[ob];
            out[base + 1] = g_boxes[ob + 1];
            out[base + 2] = g_boxes[ob + 2];
            out[base + 3] = g_boxes[ob + 3];
            out[base + 4] = ov ? g_score[n*KP + j] : 0.0f;
        }
        int lb = Nn*POST*5 + n*POST + t;
        if (lb < out_size) out[lb] = ov ? (float)g_label[n*KP + j] : 0.0f;
        int vb = Nn*POST*5 + Nn*POST + n*POST + t;
        if (vb < out_size) out[vb] = ov ? 1.0f : 0.0f;
    }
    // cleanup for next graph replay (deterministic: zero before, zero after)
    if (t < FINE) g_fine[n*FINE + t] = 0u;
    if (t == 64) { g_scnt[n] = 0; g_fbforce[n] = 0; }
}

extern "C" void kernel_launch(void* const* d_in, const int* in_sizes, int n_in,
                              void* d_out, int out_size) {
    const float* cls  = (const float*)d_in[0];
    const float* reg  = (const float*)d_in[1];
    const float* ctr  = (const float*)d_in[2];
    const float* pts  = (const float*)d_in[3];
    const float* imsz = (const float*)d_in[4];

    k_hist<<<dim3(250, 8), 256>>>(cls, ctr);
    k_sortdecode<<<8, 1024>>>(cls, ctr, reg, pts, imsz);
    k_mask<<<272, 256>>>();
    k_scanout<<<8, 256>>>((float*)d_out, out_size);
}

// round 12
// speedup vs baseline: 1.2951x; 1.2951x over previous
#include <cuda_runtime.h>
#include <cstdint>

typedef unsigned long long u64;
typedef unsigned int u32;

#define Nn 8
#define Cc 80
#define HWp 25600
#define PER_IMG (Cc*HWp)        // 2048000
#define FINE 64
#define FINE_BASE 8089          // (SPEC_BITS >> 17)
#define CAP 4096
#define CAP_SPEC 65536
#define KP 1024
#define KK 1000
#define POST 100
#define SPEC_BITS 0x3F333333u   /* bits of 0.70f */
#define REJECT_X 0.8400f        /* conservative: sigmoid(0.84)=0.6985 < 0.70 */
#define CSTAGE 4096
#define SSTAGE 512
#define TILE_JOBS 136           /* 16*17/2 upper-triangular 64x64 tiles */

// ---------------- scratch (device globals; zero-init; counters re-zeroed by k_scanout) ----
__device__ u32   g_fine[Nn*FINE];
__device__ int   g_scnt[Nn];
__device__ int   g_fbforce[Nn];
__device__ u64   g_spec[Nn*CAP_SPEC];
__device__ float g_score[Nn*KP];
__device__ float g_boxes[Nn*KP*4];
__device__ int   g_label[Nn*KP];
__device__ u32   g_validw[Nn*32];
__device__ float g_maxo[Nn];
__device__ u64   g_mask[Nn*KP*16];

__device__ __forceinline__ float sigmoidf_(float x) {
    return 1.0f / (1.0f + expf(-x));
}

// ---------------- pass 1: stream cls, warp-aggregated compact, dense sigmoid, fine hist ----
__global__ void __launch_bounds__(256) k_hist(const float* __restrict__ cls,
                                              const float* __restrict__ ctr) {
    __shared__ float sx[CSTAGE];
    __shared__ u32   se[CSTAGE];
    __shared__ u64   stage[SSTAGE];
    __shared__ u32   fine[FINE];
    __shared__ int cstage_n, sstage_n, sbase;
    if (threadIdx.x < FINE) fine[threadIdx.x] = 0;
    if (threadIdx.x == 0) { cstage_n = 0; sstage_n = 0; }
    __syncthreads();
    int n = blockIdx.y;
    u32 lane = threadIdx.x & 31;
    u32 lt_mask = (1u << lane) - 1u;
    const float4* cls4 = (const float4*)(cls + (size_t)n*PER_IMG);
    int t4 = blockIdx.x*2048 + threadIdx.x;
    // Phase A: stream + warp-aggregated compact
    #pragma unroll
    for (int it = 0; it < 8; it++, t4 += 256) {
        float4 x = cls4[t4];
        int e = t4*4;
        float pv[4] = {x.x, x.y, x.z, x.w};
        #pragma unroll
        for (int k = 0; k < 4; k++) {
            bool pred = (pv[k] >= REJECT_X);
            u32 ballot = __ballot_sync(0xffffffffu, pred);
            if (ballot) {
                int base;
                if (lane == 0) base = atomicAdd(&cstage_n, __popc(ballot));
                base = __shfl_sync(0xffffffffu, base, 0);
                if (pred) {
                    int pos = base + __popc(ballot & lt_mask);
                    if (pos < CSTAGE) { sx[pos] = pv[k]; se[pos] = (u32)(e + k); }
                }
            }
        }
    }
    __syncthreads();
    int m = cstage_n; if (m > CSTAGE) m = CSTAGE;
    // Phase B: dense sigmoid on compacted list
    const float* ctrn = ctr + n*HWp;
    for (int i = threadIdx.x; i < m; i += 256) {
        float xv = sx[i];
        u32 e = se[i];
        u32 c = e / (u32)HWp;
        u32 pix = e - c*(u32)HWp;
        float p = sigmoidf_(xv);
        float cv = sigmoidf_(ctrn[pix]);
        float s = p*cv;
        u32 sb = __float_as_uint(s);
        if (p > 0.05f && sb >= SPEC_BITS) {
            atomicAdd(&fine[(sb >> 17) - FINE_BASE], 1u);
            u64 key = (((u64)(~sb)) << 32) | (u64)(pix*80u + c);
            int pos = atomicAdd(&sstage_n, 1);
            if (pos < SSTAGE) stage[pos] = key;
            else {
                int gp = atomicAdd(&g_scnt[n], 1);
                if (gp < CAP_SPEC) g_spec[n*CAP_SPEC + gp] = key;
            }
        }
    }
    __syncthreads();
    if (threadIdx.x < FINE) {
        u32 v = fine[threadIdx.x];
        if (v) atomicAdd(&g_fine[n*FINE + threadIdx.x], v);
    }
    int sm = sstage_n < SSTAGE ? sstage_n : SSTAGE;
    if (threadIdx.x == 0 && sm > 0) sbase = atomicAdd(&g_scnt[n], sm);
    __syncthreads();
    for (int i = threadIdx.x; i < sm; i += 256) {
        int gp = sbase + i;
        if (gp < CAP_SPEC) g_spec[n*CAP_SPEC + gp] = stage[i];
    }
    if (threadIdx.x == 0 && cstage_n > CSTAGE) g_fbforce[n] = 1;
}

// ---------------- fused threshold + filter + bitonic sort + box decode + max_c ----------
__global__ void __launch_bounds__(1024) k_sortdecode(const float* __restrict__ cls,
                                                     const float* __restrict__ ctr,
                                                     const float* __restrict__ reg,
                                                     const float* __restrict__ pts,
                                                     const float* __restrict__ imsz) {
    __shared__ u64 sk[CAP];           // reused as u32[8192] hist in parachute
    __shared__ float red[1024];
    __shared__ int cnt_s;
    __shared__ int fb_s;
    __shared__ u32 tb_s;
    int n = blockIdx.x, tid = threadIdx.x;
    // threshold from fine histogram (fast path)
    if (tid == 0) {
        u32 cum = 0; int fstar = -1;
        for (int f = FINE - 1; f >= 1; f--) {
            cum += g_fine[n*FINE + f];
            if (cum >= (u32)KK) { fstar = f; break; }
        }
        int fb = (fstar < 0) || (g_scnt[n] > CAP_SPEC) || g_fbforce[n];
        fb_s = fb;
        tb_s = fb ? 0u : (((u32)(FINE_BASE + fstar)) << 17);
        cnt_s = 0;
    }
    __syncthreads();
    if (fb_s) {
        // parachute: exact full-range histogram using sk as u32[8192]
        u32* h = (u32*)sk;
        for (int i = tid; i < 8192; i += 1024) h[i] = 0;
        __syncthreads();
        const float* c0 = cls + (size_t)n*PER_IMG;
        const float* ctrn = ctr + n*HWp;
        for (int e = tid; e < PER_IMG; e += 1024) {
            int c = e / HWp; int pix = e - c*HWp;
            float p = sigmoidf_(c0[e]);
            if (p > 0.05f) {
                float cv = sigmoidf_(ctrn[pix]);
                u32 sb = __float_as_uint(p*cv);
                atomicAdd(&h[sb >> 17], 1u);
            }
        }
        __syncthreads();
        if (tid == 0) {
            u32 cum = 0; u32 tb = 0;
            for (int b = 8191; b >= 0; b--) {
                cum += h[b];
                if (cum >= (u32)KK) { tb = ((u32)b) << 17; break; }
            }
            tb_s = tb;
        }
        __syncthreads();
    }
    for (int i = tid; i < CAP; i += 1024) sk[i] = ~0ULL;
    __syncthreads();
    u32 tb = tb_s;
    if (!fb_s) {
        int m = g_scnt[n];
        for (int i = tid; i < m; i += 1024) {
            u64 key = g_spec[n*CAP_SPEC + i];
            u32 sb = ~((u32)(key >> 32));
            if (sb >= tb) {
                int pos = atomicAdd(&cnt_s, 1);
                if (pos < CAP) sk[pos] = key;
            }
        }
    } else {
        const float* c0 = cls + (size_t)n*PER_IMG;
        const float* ctrn = ctr + n*HWp;
        for (int e = tid; e < PER_IMG; e += 1024) {
            int c = e / HWp; int pix = e - c*HWp;
            float p = sigmoidf_(c0[e]);
            if (p > 0.05f) {
                float cv = sigmoidf_(ctrn[pix]);
                float s = p*cv;
                u32 sb = __float_as_uint(s);
                if (sb >= tb) {
                    int pos = atomicAdd(&cnt_s, 1);
                    if (pos < CAP) sk[pos] = (((u64)(~sb)) << 32) | (u64)((u32)pix*80u + (u32)c);
                }
            }
        }
    }
    __syncthreads();
    int cnt = cnt_s; if (cnt > CAP) cnt = CAP;
    int S = (cnt <= 2048) ? 2048 : 4096;
    for (int k2 = 2; k2 <= S; k2 <<= 1) {
        for (int j = k2 >> 1; j > 0; j >>= 1) {
            for (int i = tid; i < S; i += 1024) {
                int p = i ^ j;
                if (p > i) {
                    u64 a = sk[i], b = sk[p];
                    bool up = ((i & k2) == 0);
                    if ((a > b) == up) { sk[i] = b; sk[p] = a; }
                }
            }
            __syncthreads();
        }
    }
    float w1 = imsz[n*2] - 1.0f;
    float h1 = imsz[n*2 + 1] - 1.0f;
    const float* rg = reg + (size_t)n*4*HWp;
    float mx = 0.0f;
    {
        int r = tid;                       // KP == blockDim == 1024
        u64 key = sk[r];
        float val; int valid; u32 idx;
        if (key == ~0ULL || r >= KK) { val = -1.0f; valid = 0; idx = 0; }
        else {
            u32 sb = ~((u32)(key >> 32));
            val = __uint_as_float(sb);
            idx = (u32)key;
            valid = (val >= 0.0f) ? 1 : 0;
        }
        u32 c = idx % 80u;
        u32 loc = idx / 80u;
        float px = pts[loc*2], py = pts[loc*2 + 1];
        float d0 = rg[loc], d1 = rg[HWp + loc], d2 = rg[2*HWp + loc], d3 = rg[3*HWp + loc];
        float x1 = fminf(fmaxf(px - d0, 0.0f), w1);
        float y1 = fminf(fmaxf(py - d1, 0.0f), h1);
        float x2 = fminf(fmaxf(px + d2, 0.0f), w1);
        float y2 = fminf(fmaxf(py + d3, 0.0f), h1);
        int o = (n*KP + r)*4;
        g_boxes[o] = x1; g_boxes[o+1] = y1; g_boxes[o+2] = x2; g_boxes[o+3] = y2;
        g_label[n*KP + r] = (int)c + 1;
        g_score[n*KP + r] = valid ? sqrtf(fmaxf(val, 0.0f)) : -1.0f;
        // valid bitmap via ballot: 32 warps x 32 lanes = 1024 entries
        u32 bal = __ballot_sync(0xffffffffu, valid != 0);
        if ((tid & 31) == 0) g_validw[n*32 + (tid >> 5)] = bal;
        mx = valid ? fmaxf(fmaxf(x1, x2), fmaxf(y1, y2)) : 0.0f;
    }
    red[tid] = mx;
    __syncthreads();
    for (int s = 512; s > 0; s >>= 1) {
        if (tid < s) red[tid] = fmaxf(red[tid], red[tid + s]);
        __syncthreads();
    }
    if (tid == 0) g_maxo[n] = red[0] + 1.0f;
}

// ---------------- dense triangular IoU tiles: 4 tile-jobs per 256-thread block ----------
__global__ void __launch_bounds__(256) k_mask() {
    int jobLocal = threadIdx.x >> 6;       // 0..3
    int t = threadIdx.x & 63;
    int job = blockIdx.x*4 + jobLocal;     // 0..1087
    int n = job / TILE_JOBS;
    int q = job - n*TILE_JOBS;
    int ti = 0;
    for (int r = 0; r < 16; r++) {
        int cnt = 16 - r;
        if (q < cnt) { ti = r; break; }
        q -= cnt;
    }
    int tj = ti + q;
    float maxo = g_maxo[n];
    int i = ti*64 + t;
    int oi = (n*KP + i)*4;
    float offi = (float)g_label[n*KP + i] * maxo;
    float ax1 = g_boxes[oi]   + offi;
    float ay1 = g_boxes[oi+1] + offi;
    float ax2 = g_boxes[oi+2] + offi;
    float ay2 = g_boxes[oi+3] + offi;
    float areai = (ax2 - ax1)*(ay2 - ay1);
    __shared__ float sb[4][64][5];
    int j0 = tj*64 + t;
    int oj = (n*KP + j0)*4;
    float offj = (float)g_label[n*KP + j0] * maxo;
    float bx1 = g_boxes[oj]   + offj;
    float by1 = g_boxes[oj+1] + offj;
    float bx2 = g_boxes[oj+2] + offj;
    float by2 = g_boxes[oj+3] + offj;
    sb[jobLocal][t][0] = bx1;
    sb[jobLocal][t][1] = by1;
    sb[jobLocal][t][2] = bx2;
    sb[jobLocal][t][3] = by2;
    sb[jobLocal][t][4] = (bx2 - bx1)*(by2 - by1);
    __syncthreads();
    u64 bits = 0;
    if (i < KK) {
        int jbase = tj*64;
        const float (*sj)[5] = sb[jobLocal];
        #pragma unroll 4
        for (int jj = 0; jj < 64; jj++) {
            int j = jbase + jj;
            if (j <= i || j >= KK) continue;
            float xx1 = fmaxf(ax1, sj[jj][0]);
            float yy1 = fmaxf(ay1, sj[jj][1]);
            float xx2 = fminf(ax2, sj[jj][2]);
            float yy2 = fminf(ay2, sj[jj][3]);
            float inter = fmaxf(xx2 - xx1, 0.0f)*fmaxf(yy2 - yy1, 0.0f);
            float den = fmaxf(areai + sj[jj][4] - inter, 1e-6f);
            if (inter / den > 0.6f) bits |= 1ull << jj;
        }
    }
    g_mask[(size_t)(n*KP + i)*16 + tj] = bits;
}

// ---------------- fused NMS scan + top-100 output + counter cleanup ----------------
// Warp-0-only scan: g_mask aliased as u32[1024][32]; lane t owns rem_t in a register
// and loads column-t words (coalesced per row). The diag words of chunk c live in
// lane c's registers, so the serial resolver rotates across lanes — zero LDS in the
// chain, zero __syncthreads() in the loop, only __syncwarp() + one shared broadcast.
__global__ void __launch_bounds__(256, 1) k_scanout(float* __restrict__ out, int out_size) {
    int n = blockIdx.x, t = threadIdx.x;
    __shared__ u32 keep_s[32];
    const u32* gm32 = (const u32*)g_mask;
    if (t < 32) {
        u32 rem = ~g_validw[n*32 + t];     // suppressed-or-invalid bits start set
        for (int c = 0; c < 32; c++) {
            // lane t loads word t of rows c*32 .. c*32+31 (coalesced per row)
            u32 m[32];
            const u32* rowbase = gm32 + ((size_t)(n*KP + c*32))*32 + t;
            #pragma unroll
            for (int b = 0; b < 32; b++) m[b] = rowbase[b*32];
            if (t == c) {
                // lane c holds this chunk's diag words in m[]: serial resolve in regs
                u32 rcur = rem, kb = 0;
                #pragma unroll
                for (int b = 0; b < 32; b++) {
                    u32 dead = (u32)(((int)(rcur << (31 - b))) >> 31); // all-ones if bit b set
                    kb |= ~dead & (1u << b);
                    rcur |= m[b] & ~dead;
                }
                rem = rcur;
                keep_s[c] = kb;
            }
            __syncwarp();
            u32 kb = keep_s[c];
            if (t > c) {
                #pragma unroll
                for (int b = 0; b < 32; b++) {
                    u32 sel = 0u - ((kb >> b) & 1u);
                    rem |= m[b] & sel;
                }
            }
            __syncwarp();
        }
    }
    __syncthreads();
    __shared__ int offs[32], noffs[32];
    __shared__ int cnts[32], ncnts[32];
    __shared__ int list[POST];
    __shared__ int mks;
    if (t < 32) {
        u32 vmask = (t == 31) ? 0xFFu : 0xFFFFFFFFu;   // bits i < 1000
        cnts[t]  = __popc(keep_s[t]);
        ncnts[t] = __popc(~keep_s[t] & vmask);
    }
    __syncthreads();
    if (t == 0) {
        int acc = 0;
        for (int w = 0; w < 32; w++) { offs[w] = acc; acc += cnts[w]; }
        mks = acc > POST ? POST : acc;
        int acc2 = 0;
        for (int w = 0; w < 32; w++) { noffs[w] = acc2; acc2 += ncnts[w]; }
    }
    __syncthreads();
    if (t < 32) {
        u32 w = keep_s[t];
        int off = offs[t];
        while (w && off < POST) { int b = __ffs(w) - 1; list[off++] = t*32 + b; w &= w - 1; }
        u32 vmask = (t == 31) ? 0xFFu : 0xFFFFFFFFu;
        u32 nw = ~keep_s[t] & vmask;
        int noff = mks + noffs[t];
        while (nw && noff < POST) { int b = __ffs(nw) - 1; list[noff++] = t*32 + b; nw &= nw - 1; }
    }
    __syncthreads();
    if (t < POST) {
        int j = list[t];
        bool ov = t < mks;
        int ob = (n*KP + j)*4;
        int base = n*POST*5 + t*5;
        if (base + 4 < out_size) {
            out[base]     = g_boxes[ob];
            out[base + 1] = g_boxes[ob + 1];
            out[base + 2] = g_boxes[ob + 2];
            out[base + 3] = g_boxes[ob + 3];
            out[base + 4] = ov ? g_score[n*KP + j] : 0.0f;
        }
        int lb = Nn*POST*5 + n*POST + t;
        if (lb < out_size) out[lb] = ov ? (float)g_label[n*KP + j] : 0.0f;
        int vb = Nn*POST*5 + Nn*POST + n*POST + t;
        if (vb < out_size) out[vb] = ov ? 1.0f : 0.0f;
    }
    // cleanup for next graph replay (deterministic: zero before, zero after)
    if (t >= 128 && t < 128 + FINE) g_fine[n*FINE + (t - 128)] = 0u;
    if (t == 224) { g_scnt[n] = 0; g_fbforce[n] = 0; }
}

extern "C" void kernel_launch(void* const* d_in, const int* in_sizes, int n_in,
                              void* d_out, int out_size) {
    const float* cls  = (const float*)d_in[0];
    const float* reg  = (const float*)d_in[1];
    const float* ctr  = (const float*)d_in[2];
    const float* pts  = (const float*)d_in[3];
    const float* imsz = (const float*)d_in[4];

    k_hist<<<dim3(250, 8), 256>>>(cls, ctr);
    k_sortdecode<<<8, 1024>>>(cls, ctr, reg, pts, imsz);
    k_mask<<<272, 256>>>();
    k_scanout<<<8, 256>>>((float*)d_out, out_size);
}